// round 15
// baseline (speedup 1.0000x reference)
#include <cuda_runtime.h>
#include <cuda_fp16.h>

#define NN   100000
#define NE   1000000
#define NG   2048
#define HID  64
#define ODIM 128

#define SCAN_T   256
#define SCAN_C   4
#define SCAN_NPB (SCAN_T * SCAN_C)                  // 1024 nodes per block
#define SCAN_B   ((NN + SCAN_NPB - 1) / SCAN_NPB)   // 98 blocks (all co-resident)

#define H1S_STRIDE 68   // 64 + 4 pad

__device__ float  d_dinv[NN];
__device__ int    d_cnt_in[NN];    // zeroed by tail of previous run
__device__ int    d_row[NN];
__device__ int    d_fill[NN];      // zeroed by tail of previous run
__device__ int    d_csrc[NE];      // CSR: src index per slot (weight-free)
__device__ __half d_h16[NN * HID]; // x @ W1; scaled in-place by dinv in k_build_scale
__device__ __half d_g16[NN * HID]; // layer-1 out, written pre-scaled by dinv
__device__ float  d_pool[NG * HID]; // zeroed by tail of previous run
__device__ float  d_cnt[NG];        // zeroed by tail of previous run
__device__ int    d_agg[SCAN_B];    // per-block scan aggregates
__device__ int    d_ready;          // publish counter (zeroed by tail of prev run)

__device__ __forceinline__ void red_v4(float* ap, float a, float b, float c, float d) {
    asm volatile("red.global.add.v4.f32 [%0], {%1, %2, %3, %4};"
                 :: "l"(ap), "f"(a), "f"(b), "f"(c), "f"(d) : "memory");
}

__device__ __forceinline__ uint2 pack_h4(float a, float b, float c, float d) {
    __half2 lo = __floats2half2_rn(a, b);
    __half2 hi = __floats2half2_rn(c, d);
    uint2 r;
    r.x = *reinterpret_cast<unsigned*>(&lo);
    r.y = *reinterpret_cast<unsigned*>(&hi);
    return r;
}

__device__ __forceinline__ void unpack_h4(uint2 u, float& a, float& b, float& c, float& d) {
    float2 l = __half22float2(*reinterpret_cast<__half2*>(&u.x));
    float2 h = __half22float2(*reinterpret_cast<__half2*>(&u.y));
    a = l.x; b = l.y; c = h.x; d = h.y;
}

// ── 1. fused: degree histogram (edges) + h16 = x @ W1 (nodes, unscaled) ──
__global__ void __launch_bounds__(256) k_hist_xw1(const int* __restrict__ dst,
                                                  const float* __restrict__ x,
                                                  const float* __restrict__ W1) {
    __shared__ float W1s[5 * HID];
    int tid = threadIdx.x;
    for (int i = tid; i < 5 * HID; i += blockDim.x) W1s[i] = W1[i];
    __syncthreads();

    int t = blockIdx.x * blockDim.x + tid;
    if (t < NE) atomicAdd(&d_cnt_in[dst[t]], 1);

    int n = t >> 4, c = t & 15;
    if (n >= NN) return;
    float xv[5];
#pragma unroll
    for (int k = 0; k < 5; k++) xv[k] = x[n * 5 + k];
    float o[4];
#pragma unroll
    for (int j = 0; j < 4; j++) {
        float s = 0.f;
#pragma unroll
        for (int k = 0; k < 5; k++) s += xv[k] * W1s[k * HID + c * 4 + j];
        o[j] = s;
    }
    *reinterpret_cast<uint2*>(&d_h16[(size_t)n * HID + c * 4]) =
        pack_h4(o[0], o[1], o[2], o[3]);
}

// ── 2. single-pass scan + dinv ──
__global__ void __launch_bounds__(SCAN_T) k_scan() {
    __shared__ int sh[SCAN_T];
    int b = blockIdx.x, tid = threadIdx.x;
    int base = b * SCAN_NPB + tid * SCAN_C;
    int cnt[SCAN_C];
    int s = 0;
#pragma unroll
    for (int i = 0; i < SCAN_C; i++) {
        int idx = base + i;
        int cv = (idx < NN) ? d_cnt_in[idx] : 0;
        cnt[i] = cv;
        s += cv;
        if (idx < NN) d_dinv[idx] = rsqrtf((float)(cv + 1));  // +1 self-loop
    }
    sh[tid] = s;
    __syncthreads();
    for (int off = 1; off < SCAN_T; off <<= 1) {
        int t = (tid >= off) ? sh[tid - off] : 0;
        __syncthreads();
        sh[tid] += t;
        __syncthreads();
    }
    int toff = sh[tid] - s;
    int btotal = sh[SCAN_T - 1];
    __syncthreads();

    if (tid == 0) {
        d_agg[b] = btotal;
        __threadfence();
        atomicAdd(&d_ready, 1);
    }
    if (tid == 0) {
        while (*(volatile int*)&d_ready < SCAN_B) { }
    }
    __syncthreads();

    int v = (tid < SCAN_B) ? d_agg[tid] : 0;
    sh[tid] = v;
    __syncthreads();
    for (int off = 1; off < SCAN_T; off <<= 1) {
        int t = (tid >= off) ? sh[tid - off] : 0;
        __syncthreads();
        sh[tid] += t;
        __syncthreads();
    }
    int boff = (b > 0) ? sh[b - 1] : 0;

    int run = boff + toff;
#pragma unroll
    for (int i = 0; i < SCAN_C; i++) {
        int idx = base + i;
        if (idx < NN) { d_row[idx] = run; run += cnt[i]; }
    }
}

// ── 3. fused: CSR build (1 store/edge) + h16 *= dinv sweep ──
__global__ void __launch_bounds__(256) k_build_scale(const int* __restrict__ src,
                                                     const int* __restrict__ dst) {
    int t = blockIdx.x * blockDim.x + threadIdx.x;
    if (t < NE) {
        int s = src[t], d = dst[t];
        int slot = d_row[d] + atomicAdd(&d_fill[d], 1);
        d_csrc[slot] = s;
    }
    int n = t >> 4, c = t & 15;
    if (n < NN) {
        float di = d_dinv[n];
        size_t off = (size_t)n * HID + c * 4;
        uint2 u = *reinterpret_cast<uint2*>(&d_h16[off]);
        float p0, p1, p2, p3;
        unpack_h4(u, p0, p1, p2, p3);
        *reinterpret_cast<uint2*>(&d_h16[off]) =
            pack_h4(p0 * di, p1 * di, p2 * di, p3 * di);
    }
}

// CSR gather: fp16 HADD2 accumulation in 8/4-edge blocks, fp32 flush + remainder
__device__ __forceinline__ void gather_sum(const __half* __restrict__ feat,
                                           int start, int deg, int c,
                                           float& a0, float& a1, float& a2, float& a3) {
    const int cofs = c * 4;
    int j = 0;
    for (; j + 8 <= deg; j += 8) {
        __half2 s01 = __float2half2_rn(0.f), s23 = __float2half2_rn(0.f);
#pragma unroll
        for (int i = 0; i < 8; i++) {
            int s = __ldg(&d_csrc[start + j + i]);
            uint2 u = *reinterpret_cast<const uint2*>(&feat[(size_t)s * HID + cofs]);
            s01 = __hadd2(s01, *reinterpret_cast<__half2*>(&u.x));
            s23 = __hadd2(s23, *reinterpret_cast<__half2*>(&u.y));
        }
        float2 f01 = __half22float2(s01);
        float2 f23 = __half22float2(s23);
        a0 += f01.x; a1 += f01.y; a2 += f23.x; a3 += f23.y;
    }
    if (j + 4 <= deg) {
        __half2 s01 = __float2half2_rn(0.f), s23 = __float2half2_rn(0.f);
#pragma unroll
        for (int i = 0; i < 4; i++) {
            int s = __ldg(&d_csrc[start + j + i]);
            uint2 u = *reinterpret_cast<const uint2*>(&feat[(size_t)s * HID + cofs]);
            s01 = __hadd2(s01, *reinterpret_cast<__half2*>(&u.x));
            s23 = __hadd2(s23, *reinterpret_cast<__half2*>(&u.y));
        }
        float2 f01 = __half22float2(s01);
        float2 f23 = __half22float2(s23);
        a0 += f01.x; a1 += f01.y; a2 += f23.x; a3 += f23.y;
        j += 4;
    }
    for (; j < deg; j++) {
        int s = __ldg(&d_csrc[start + j]);
        uint2 u = *reinterpret_cast<const uint2*>(&feat[(size_t)s * HID + cofs]);
        float p0, p1, p2, p3;
        unpack_h4(u, p0, p1, p2, p3);
        a0 += p0; a1 += p1; a2 += p2; a3 += p3;
    }
}

// ── 4. layer 1, register-blocked GEMM: 64 nodes/block ──
__global__ void __launch_bounds__(256) k_layer1(const float* __restrict__ b1,
                                                const float* __restrict__ W2) {
    __shared__ float W2s[HID * HID];
    __shared__ float h1s[64 * H1S_STRIDE];
    __shared__ float b1s[HID];
    __shared__ float dis[64];
    int tid = threadIdx.x;
    for (int i = tid; i < HID * HID; i += 256) W2s[i] = W2[i];
    if (tid < HID) b1s[tid] = b1[tid];
    __syncthreads();

    int nl = tid >> 4, c = tid & 15;
#pragma unroll 1
    for (int sub = 0; sub < 4; sub++) {
        int lnode = sub * 16 + nl;
        int node = blockIdx.x * 64 + lnode;
        if (node < NN) {
            int start = d_row[node], deg = d_cnt_in[node];
            float a0 = 0.f, a1 = 0.f, a2 = 0.f, a3 = 0.f;
            gather_sum(d_h16, start, deg, c, a0, a1, a2, a3);
            uint2 u = *reinterpret_cast<const uint2*>(&d_h16[(size_t)node * HID + c * 4]);
            float h0, h1, h2, h3;
            unpack_h4(u, h0, h1, h2, h3);
            float di = d_dinv[node];
            h1s[lnode * H1S_STRIDE + c * 4 + 0] = fmaxf((a0 + h0) * di + b1s[c * 4 + 0], 0.f);
            h1s[lnode * H1S_STRIDE + c * 4 + 1] = fmaxf((a1 + h1) * di + b1s[c * 4 + 1], 0.f);
            h1s[lnode * H1S_STRIDE + c * 4 + 2] = fmaxf((a2 + h2) * di + b1s[c * 4 + 2], 0.f);
            h1s[lnode * H1S_STRIDE + c * 4 + 3] = fmaxf((a3 + h3) * di + b1s[c * 4 + 3], 0.f);
            if (c == 0) dis[lnode] = di;
        } else {
#pragma unroll
            for (int j = 0; j < 4; j++) h1s[lnode * H1S_STRIDE + c * 4 + j] = 0.f;
            if (c == 0) dis[lnode] = 0.f;
        }
    }
    __syncthreads();

    // phase 2: thread (g, c) computes nodes g*4..g*4+3 × cols c*4..c*4+3
    int g = tid >> 4;
    float acc[4][4] = {};
#pragma unroll 16
    for (int k = 0; k < HID; k++) {
        float4 w = *reinterpret_cast<const float4*>(&W2s[k * HID + c * 4]);
#pragma unroll
        for (int i = 0; i < 4; i++) {
            float hv = h1s[(g * 4 + i) * H1S_STRIDE + k];
            acc[i][0] += hv * w.x;
            acc[i][1] += hv * w.y;
            acc[i][2] += hv * w.z;
            acc[i][3] += hv * w.w;
        }
    }
#pragma unroll
    for (int i = 0; i < 4; i++) {
        int node = blockIdx.x * 64 + g * 4 + i;
        if (node < NN) {
            float di = dis[g * 4 + i];
            *reinterpret_cast<uint2*>(&d_g16[(size_t)node * HID + c * 4]) =
                pack_h4(acc[i][0] * di, acc[i][1] * di, acc[i][2] * di, acc[i][3] * di);
        }
    }
}

// ── 5. layer 2: h2 = relu(dinv·(Σ gs[src] + gs[n]) + b2); pool += h2 ──
__global__ void __launch_bounds__(256) k_layer2(const float* __restrict__ b2,
                                                const int* __restrict__ batch) {
    int t = blockIdx.x * blockDim.x + threadIdx.x;
    int n = t >> 4, c = t & 15;
    if (n >= NN) return;
    int start = d_row[n], deg = d_cnt_in[n];
    float a0 = 0.f, a1 = 0.f, a2 = 0.f, a3 = 0.f;
    gather_sum(d_g16, start, deg, c, a0, a1, a2, a3);
    uint2 u = *reinterpret_cast<const uint2*>(&d_g16[(size_t)n * HID + c * 4]);
    float g0, g1, g2, g3;
    unpack_h4(u, g0, g1, g2, g3);
    float di = d_dinv[n];
    float o0 = fmaxf((a0 + g0) * di + b2[c * 4 + 0], 0.f);
    float o1 = fmaxf((a1 + g1) * di + b2[c * 4 + 1], 0.f);
    float o2 = fmaxf((a2 + g2) * di + b2[c * 4 + 2], 0.f);
    float o3 = fmaxf((a3 + g3) * di + b2[c * 4 + 3], 0.f);
    int g = batch[n];
    red_v4(&d_pool[g * HID + c * 4], o0, o1, o2, o3);
    if (c == 0) atomicAdd(&d_cnt[g], 1.0f);
}

// ── 6. head + tail-restore (pool/cnt/cnt_in/fill/ready) ──
__global__ void __launch_bounds__(128) k_head(const float* __restrict__ W3,
                                              const float* __restrict__ b3,
                                              const float* __restrict__ W4,
                                              const float* __restrict__ b4,
                                              float* __restrict__ out) {
    __shared__ float p[HID];
    __shared__ float z[HID];
    int g = blockIdx.x, tid = threadIdx.x;
    if (tid < HID) {
        float cnt = fmaxf(d_cnt[g], 1.0f);
        p[tid] = d_pool[g * HID + tid] / cnt;
    }
    __syncthreads();
    if (tid < HID) d_pool[g * HID + tid] = 0.f;
    if (tid == 0)  d_cnt[g] = 0.f;
    if (g == 0 && tid == 0) d_ready = 0;
    {
        int i = g * 128 + tid;           // 262144 threads cover NN=100000
        if (i < NN) { d_cnt_in[i] = 0; d_fill[i] = 0; }
    }
    if (tid < HID) {
        float s = b3[tid];
#pragma unroll
        for (int k = 0; k < HID; k++) s += p[k] * W3[k * HID + tid];
        z[tid] = fmaxf(s, 0.f);
    }
    __syncthreads();
    float s = b4[tid];
#pragma unroll
    for (int k = 0; k < HID; k++) s += z[k] * W4[k * ODIM + tid];
    out[g * ODIM + tid] = s;
}

extern "C" void kernel_launch(void* const* d_in, const int* in_sizes, int n_in,
                              void* d_out, int out_size) {
    const float* x     = (const float*)d_in[0];
    const int*   ei    = (const int*)d_in[1];
    const int*   batch = (const int*)d_in[2];
    const float* W1 = (const float*)d_in[3];
    const float* b1 = (const float*)d_in[4];
    const float* W2 = (const float*)d_in[5];
    const float* b2 = (const float*)d_in[6];
    const float* W3 = (const float*)d_in[7];
    const float* b3 = (const float*)d_in[8];
    const float* W4 = (const float*)d_in[9];
    const float* b4 = (const float*)d_in[10];
    float* out = (float*)d_out;

    const int* src = ei;
    const int* dst = ei + NE;

    k_hist_xw1<<<(NN * 16 + 255) / 256, 256>>>(dst, x, W1);      // 0
    k_scan<<<SCAN_B, SCAN_T>>>();                                // 1
    k_build_scale<<<(NN * 16 + 255) / 256, 256>>>(src, dst);     // 2
    k_layer1<<<(NN + 63) / 64, 256>>>(b1, W2);                   // 3 ← profiled slot
    k_layer2<<<(NN * 16 + 255) / 256, 256>>>(b2, batch);         // 4
    k_head<<<NG, 128>>>(W3, b3, W4, b4, out);                    // 5
}

// round 16
// speedup vs baseline: 1.0352x; 1.0352x over previous
#include <cuda_runtime.h>
#include <cuda_fp16.h>

#define NN   100000
#define NE   1000000
#define NG   2048
#define HID  64
#define ODIM 128

#define SCAN_T   256
#define SCAN_C   4
#define SCAN_NPB (SCAN_T * SCAN_C)                  // 1024 nodes per block
#define SCAN_B   ((NN + SCAN_NPB - 1) / SCAN_NPB)   // 98 blocks (all co-resident)

#define H1S_STRIDE 68   // 64 + 4 pad

__device__ float  d_dinv[NN];
__device__ int    d_cnt_in[NN];    // zeroed by tail of previous run
__device__ int    d_row[NN];
__device__ int    d_fill[NN];      // zeroed by tail of previous run
__device__ int    d_csrc[NE];      // CSR: src index per slot (weight-free)
__device__ __half d_h16[NN * HID]; // x @ W1; scaled in-place by dinv in k_build_scale
__device__ __half d_t16[NN * HID]; // h1 = relu(...) (fp16, GEMM input)
__device__ __half d_g16[NN * HID]; // layer-1 out, written pre-scaled by dinv
__device__ float  d_pool[NG * HID]; // zeroed by tail of previous run
__device__ float  d_cnt[NG];        // zeroed by tail of previous run
__device__ int    d_agg[SCAN_B];    // per-block scan aggregates
__device__ int    d_ready;          // publish counter (zeroed by tail of prev run)

__device__ __forceinline__ void red_v4(float* ap, float a, float b, float c, float d) {
    asm volatile("red.global.add.v4.f32 [%0], {%1, %2, %3, %4};"
                 :: "l"(ap), "f"(a), "f"(b), "f"(c), "f"(d) : "memory");
}

__device__ __forceinline__ uint2 pack_h4(float a, float b, float c, float d) {
    __half2 lo = __floats2half2_rn(a, b);
    __half2 hi = __floats2half2_rn(c, d);
    uint2 r;
    r.x = *reinterpret_cast<unsigned*>(&lo);
    r.y = *reinterpret_cast<unsigned*>(&hi);
    return r;
}

__device__ __forceinline__ void unpack_h4(uint2 u, float& a, float& b, float& c, float& d) {
    float2 l = __half22float2(*reinterpret_cast<__half2*>(&u.x));
    float2 h = __half22float2(*reinterpret_cast<__half2*>(&u.y));
    a = l.x; b = l.y; c = h.x; d = h.y;
}

// ── 1. fused: degree histogram (edges) + h16 = x @ W1 (nodes, unscaled) ──
__global__ void __launch_bounds__(256) k_hist_xw1(const int* __restrict__ dst,
                                                  const float* __restrict__ x,
                                                  const float* __restrict__ W1) {
    __shared__ float W1s[5 * HID];
    int tid = threadIdx.x;
    for (int i = tid; i < 5 * HID; i += blockDim.x) W1s[i] = W1[i];
    __syncthreads();

    int t = blockIdx.x * blockDim.x + tid;
    if (t < NE) atomicAdd(&d_cnt_in[dst[t]], 1);

    int n = t >> 4, c = t & 15;
    if (n >= NN) return;
    float xv[5];
#pragma unroll
    for (int k = 0; k < 5; k++) xv[k] = x[n * 5 + k];
    float o[4];
#pragma unroll
    for (int j = 0; j < 4; j++) {
        float s = 0.f;
#pragma unroll
        for (int k = 0; k < 5; k++) s += xv[k] * W1s[k * HID + c * 4 + j];
        o[j] = s;
    }
    *reinterpret_cast<uint2*>(&d_h16[(size_t)n * HID + c * 4]) =
        pack_h4(o[0], o[1], o[2], o[3]);
}

// ── 2. single-pass scan + dinv ──
__global__ void __launch_bounds__(SCAN_T) k_scan() {
    __shared__ int sh[SCAN_T];
    int b = blockIdx.x, tid = threadIdx.x;
    int base = b * SCAN_NPB + tid * SCAN_C;
    int cnt[SCAN_C];
    int s = 0;
#pragma unroll
    for (int i = 0; i < SCAN_C; i++) {
        int idx = base + i;
        int cv = (idx < NN) ? d_cnt_in[idx] : 0;
        cnt[i] = cv;
        s += cv;
        if (idx < NN) d_dinv[idx] = rsqrtf((float)(cv + 1));  // +1 self-loop
    }
    sh[tid] = s;
    __syncthreads();
    for (int off = 1; off < SCAN_T; off <<= 1) {
        int t = (tid >= off) ? sh[tid - off] : 0;
        __syncthreads();
        sh[tid] += t;
        __syncthreads();
    }
    int toff = sh[tid] - s;
    int btotal = sh[SCAN_T - 1];
    __syncthreads();

    if (tid == 0) {
        d_agg[b] = btotal;
        __threadfence();
        atomicAdd(&d_ready, 1);
    }
    if (tid == 0) {
        while (*(volatile int*)&d_ready < SCAN_B) { }
    }
    __syncthreads();

    int v = (tid < SCAN_B) ? d_agg[tid] : 0;
    sh[tid] = v;
    __syncthreads();
    for (int off = 1; off < SCAN_T; off <<= 1) {
        int t = (tid >= off) ? sh[tid - off] : 0;
        __syncthreads();
        sh[tid] += t;
        __syncthreads();
    }
    int boff = (b > 0) ? sh[b - 1] : 0;

    int run = boff + toff;
#pragma unroll
    for (int i = 0; i < SCAN_C; i++) {
        int idx = base + i;
        if (idx < NN) { d_row[idx] = run; run += cnt[i]; }
    }
}

// ── 3. fused: CSR build (1 store/edge) + h16 *= dinv sweep ──
__global__ void __launch_bounds__(256) k_build_scale(const int* __restrict__ src,
                                                     const int* __restrict__ dst) {
    int t = blockIdx.x * blockDim.x + threadIdx.x;
    if (t < NE) {
        int s = src[t], d = dst[t];
        int slot = d_row[d] + atomicAdd(&d_fill[d], 1);
        d_csrc[slot] = s;
    }
    int n = t >> 4, c = t & 15;
    if (n < NN) {
        float di = d_dinv[n];
        size_t off = (size_t)n * HID + c * 4;
        uint2 u = *reinterpret_cast<uint2*>(&d_h16[off]);
        float p0, p1, p2, p3;
        unpack_h4(u, p0, p1, p2, p3);
        *reinterpret_cast<uint2*>(&d_h16[off]) =
            pack_h4(p0 * di, p1 * di, p2 * di, p3 * di);
    }
}

// CSR gather: pure sum of pre-scaled fp16 rows, 4-way unrolled, fp32 accumulate
__device__ __forceinline__ void gather_sum(const __half* __restrict__ feat,
                                           int start, int deg, int c,
                                           float& a0, float& a1, float& a2, float& a3) {
    int j = 0;
    for (; j + 4 <= deg; j += 4) {
        int s0 = __ldg(&d_csrc[start + j + 0]);
        int s1 = __ldg(&d_csrc[start + j + 1]);
        int s2 = __ldg(&d_csrc[start + j + 2]);
        int s3 = __ldg(&d_csrc[start + j + 3]);
        uint2 u0 = *reinterpret_cast<const uint2*>(&feat[(size_t)s0 * HID + c * 4]);
        uint2 u1 = *reinterpret_cast<const uint2*>(&feat[(size_t)s1 * HID + c * 4]);
        uint2 u2 = *reinterpret_cast<const uint2*>(&feat[(size_t)s2 * HID + c * 4]);
        uint2 u3 = *reinterpret_cast<const uint2*>(&feat[(size_t)s3 * HID + c * 4]);
        float p0, p1, p2, p3, q0, q1, q2, q3, r0, r1, r2, r3, t0, t1, t2, t3;
        unpack_h4(u0, p0, p1, p2, p3);
        unpack_h4(u1, q0, q1, q2, q3);
        unpack_h4(u2, r0, r1, r2, r3);
        unpack_h4(u3, t0, t1, t2, t3);
        a0 += (p0 + q0) + (r0 + t0);
        a1 += (p1 + q1) + (r1 + t1);
        a2 += (p2 + q2) + (r2 + t2);
        a3 += (p3 + q3) + (r3 + t3);
    }
    for (; j < deg; j++) {
        int s = __ldg(&d_csrc[start + j]);
        uint2 u = *reinterpret_cast<const uint2*>(&feat[(size_t)s * HID + c * 4]);
        float p0, p1, p2, p3;
        unpack_h4(u, p0, p1, p2, p3);
        a0 += p0; a1 += p1; a2 += p2; a3 += p3;
    }
}

// ── 4a. layer-1 gather (high occupancy): t16 = relu(dinv·(Σ hs + hs[n]) + b1) ──
__global__ void __launch_bounds__(256) k_gather1(const float* __restrict__ b1) {
    int t = blockIdx.x * blockDim.x + threadIdx.x;
    int n = t >> 4, c = t & 15;
    if (n >= NN) return;
    int start = d_row[n], deg = d_cnt_in[n];
    float a0 = 0.f, a1 = 0.f, a2 = 0.f, a3 = 0.f;
    gather_sum(d_h16, start, deg, c, a0, a1, a2, a3);
    uint2 u = *reinterpret_cast<const uint2*>(&d_h16[(size_t)n * HID + c * 4]);
    float h0, h1, h2, h3;
    unpack_h4(u, h0, h1, h2, h3);
    float di = d_dinv[n];
    float o0 = fmaxf((a0 + h0) * di + __ldg(&b1[c * 4 + 0]), 0.f);
    float o1 = fmaxf((a1 + h1) * di + __ldg(&b1[c * 4 + 1]), 0.f);
    float o2 = fmaxf((a2 + h2) * di + __ldg(&b1[c * 4 + 2]), 0.f);
    float o3 = fmaxf((a3 + h3) * di + __ldg(&b1[c * 4 + 3]), 0.f);
    *reinterpret_cast<uint2*>(&d_t16[(size_t)n * HID + c * 4]) =
        pack_h4(o0, o1, o2, o3);
}

// ── 4b. layer-1 GEMM (register-blocked, 64 nodes/block): g16 = (t16 @ W2)·dinv ──
__global__ void __launch_bounds__(256) k_gemm(const float* __restrict__ W2) {
    __shared__ float W2s[HID * HID];
    __shared__ float h1s[64 * H1S_STRIDE];
    __shared__ float dis[64];
    int tid = threadIdx.x;
    int base = blockIdx.x * 64;
    for (int i = tid; i < HID * HID; i += 256) W2s[i] = W2[i];
    for (int i = tid; i < 64 * 16; i += 256) {
        int ln = i >> 4, c = i & 15;
        int node = base + ln;
        float p0 = 0.f, p1 = 0.f, p2 = 0.f, p3 = 0.f;
        if (node < NN) {
            uint2 u = *reinterpret_cast<const uint2*>(&d_t16[(size_t)node * HID + c * 4]);
            unpack_h4(u, p0, p1, p2, p3);
        }
        h1s[ln * H1S_STRIDE + c * 4 + 0] = p0;
        h1s[ln * H1S_STRIDE + c * 4 + 1] = p1;
        h1s[ln * H1S_STRIDE + c * 4 + 2] = p2;
        h1s[ln * H1S_STRIDE + c * 4 + 3] = p3;
    }
    if (tid < 64) dis[tid] = (base + tid < NN) ? d_dinv[base + tid] : 0.f;
    __syncthreads();

    int g = tid >> 4, c = tid & 15;
    float acc[4][4] = {};
#pragma unroll 16
    for (int k = 0; k < HID; k++) {
        float4 w = *reinterpret_cast<const float4*>(&W2s[k * HID + c * 4]);
#pragma unroll
        for (int i = 0; i < 4; i++) {
            float hv = h1s[(g * 4 + i) * H1S_STRIDE + k];
            acc[i][0] += hv * w.x;
            acc[i][1] += hv * w.y;
            acc[i][2] += hv * w.z;
            acc[i][3] += hv * w.w;
        }
    }
#pragma unroll
    for (int i = 0; i < 4; i++) {
        int node = base + g * 4 + i;
        if (node < NN) {
            float di = dis[g * 4 + i];
            *reinterpret_cast<uint2*>(&d_g16[(size_t)node * HID + c * 4]) =
                pack_h4(acc[i][0] * di, acc[i][1] * di, acc[i][2] * di, acc[i][3] * di);
        }
    }
}

// ── 5. layer 2: h2 = relu(dinv·(Σ gs[src] + gs[n]) + b2); pool += h2 ──
__global__ void __launch_bounds__(256) k_layer2(const float* __restrict__ b2,
                                                const int* __restrict__ batch) {
    int t = blockIdx.x * blockDim.x + threadIdx.x;
    int n = t >> 4, c = t & 15;
    if (n >= NN) return;
    int start = d_row[n], deg = d_cnt_in[n];
    float a0 = 0.f, a1 = 0.f, a2 = 0.f, a3 = 0.f;
    gather_sum(d_g16, start, deg, c, a0, a1, a2, a3);
    uint2 u = *reinterpret_cast<const uint2*>(&d_g16[(size_t)n * HID + c * 4]);
    float g0, g1, g2, g3;
    unpack_h4(u, g0, g1, g2, g3);
    float di = d_dinv[n];
    float o0 = fmaxf((a0 + g0) * di + b2[c * 4 + 0], 0.f);
    float o1 = fmaxf((a1 + g1) * di + b2[c * 4 + 1], 0.f);
    float o2 = fmaxf((a2 + g2) * di + b2[c * 4 + 2], 0.f);
    float o3 = fmaxf((a3 + g3) * di + b2[c * 4 + 3], 0.f);
    int g = batch[n];
    red_v4(&d_pool[g * HID + c * 4], o0, o1, o2, o3);
    if (c == 0) atomicAdd(&d_cnt[g], 1.0f);
}

// ── 6. head + tail-restore (pool/cnt/cnt_in/fill/ready) ──
__global__ void __launch_bounds__(128) k_head(const float* __restrict__ W3,
                                              const float* __restrict__ b3,
                                              const float* __restrict__ W4,
                                              const float* __restrict__ b4,
                                              float* __restrict__ out) {
    __shared__ float p[HID];
    __shared__ float z[HID];
    int g = blockIdx.x, tid = threadIdx.x;
    if (tid < HID) {
        float cnt = fmaxf(d_cnt[g], 1.0f);
        p[tid] = d_pool[g * HID + tid] / cnt;
    }
    __syncthreads();
    if (tid < HID) d_pool[g * HID + tid] = 0.f;
    if (tid == 0)  d_cnt[g] = 0.f;
    if (g == 0 && tid == 0) d_ready = 0;
    {
        int i = g * 128 + tid;           // 262144 threads cover NN=100000
        if (i < NN) { d_cnt_in[i] = 0; d_fill[i] = 0; }
    }
    if (tid < HID) {
        float s = b3[tid];
#pragma unroll
        for (int k = 0; k < HID; k++) s += p[k] * W3[k * HID + tid];
        z[tid] = fmaxf(s, 0.f);
    }
    __syncthreads();
    float s = b4[tid];
#pragma unroll
    for (int k = 0; k < HID; k++) s += z[k] * W4[k * ODIM + tid];
    out[g * ODIM + tid] = s;
}

extern "C" void kernel_launch(void* const* d_in, const int* in_sizes, int n_in,
                              void* d_out, int out_size) {
    const float* x     = (const float*)d_in[0];
    const int*   ei    = (const int*)d_in[1];
    const int*   batch = (const int*)d_in[2];
    const float* W1 = (const float*)d_in[3];
    const float* b1 = (const float*)d_in[4];
    const float* W2 = (const float*)d_in[5];
    const float* b2 = (const float*)d_in[6];
    const float* W3 = (const float*)d_in[7];
    const float* b3 = (const float*)d_in[8];
    const float* W4 = (const float*)d_in[9];
    const float* b4 = (const float*)d_in[10];
    float* out = (float*)d_out;

    const int* src = ei;
    const int* dst = ei + NE;

    k_hist_xw1<<<(NN * 16 + 255) / 256, 256>>>(dst, x, W1);      // 0
    k_scan<<<SCAN_B, SCAN_T>>>();                                // 1
    k_build_scale<<<(NN * 16 + 255) / 256, 256>>>(src, dst);     // 2
    k_gather1<<<(NN * 16 + 255) / 256, 256>>>(b1);               // 3 ← profiled slot
    k_gemm<<<(NN + 63) / 64, 256>>>(W2);                         // 4
    k_layer2<<<(NN * 16 + 255) / 256, 256>>>(b2, batch);         // 5
    k_head<<<NG, 128>>>(W3, b3, W4, b4, out);                    // 6
}

// round 17
// speedup vs baseline: 1.0563x; 1.0204x over previous
#include <cuda_runtime.h>
#include <cuda_fp16.h>

#define NN   100000
#define NE   1000000
#define NG   2048
#define HID  64
#define ODIM 128

#define SCAN_T   256
#define SCAN_C   4
#define SCAN_NPB (SCAN_T * SCAN_C)                  // 1024 nodes per block
#define SCAN_B   ((NN + SCAN_NPB - 1) / SCAN_NPB)   // 98 blocks (all co-resident)

#define H1S_STRIDE 68   // 64 + 4 pad

__device__ float  d_dinv[NN];
__device__ int    d_cnt_in[NN];    // zeroed by tail of previous run
__device__ int    d_row[NN];
__device__ int    d_fill[NN];      // zeroed by tail of previous run
__device__ int    d_csrc[NE];      // CSR: src BYTE OFFSET (s*128) per slot
__device__ __half d_h16[NN * HID]; // x @ W1; scaled in-place by dinv in k_build_scale
__device__ __half d_t16[NN * HID]; // h1 = relu(...) (fp16, GEMM input)
__device__ __half d_g16[NN * HID]; // layer-1 out, written pre-scaled by dinv
__device__ float  d_pool[NG * HID]; // zeroed by tail of previous run
__device__ float  d_cnt[NG];        // zeroed by tail of previous run
__device__ int    d_agg[SCAN_B];    // per-block scan aggregates
__device__ int    d_ready;          // publish counter (zeroed by tail of prev run)

__device__ __forceinline__ void red_v4(float* ap, float a, float b, float c, float d) {
    asm volatile("red.global.add.v4.f32 [%0], {%1, %2, %3, %4};"
                 :: "l"(ap), "f"(a), "f"(b), "f"(c), "f"(d) : "memory");
}

__device__ __forceinline__ uint2 pack_h4(float a, float b, float c, float d) {
    __half2 lo = __floats2half2_rn(a, b);
    __half2 hi = __floats2half2_rn(c, d);
    uint2 r;
    r.x = *reinterpret_cast<unsigned*>(&lo);
    r.y = *reinterpret_cast<unsigned*>(&hi);
    return r;
}

__device__ __forceinline__ void unpack_h4(uint2 u, float& a, float& b, float& c, float& d) {
    float2 l = __half22float2(*reinterpret_cast<__half2*>(&u.x));
    float2 h = __half22float2(*reinterpret_cast<__half2*>(&u.y));
    a = l.x; b = l.y; c = h.x; d = h.y;
}

// accumulate 8 halves (uint4) into 8 fp32
__device__ __forceinline__ void acc_h8(uint4 u, float* a) {
    float2 f0 = __half22float2(*reinterpret_cast<__half2*>(&u.x));
    float2 f1 = __half22float2(*reinterpret_cast<__half2*>(&u.y));
    float2 f2 = __half22float2(*reinterpret_cast<__half2*>(&u.z));
    float2 f3 = __half22float2(*reinterpret_cast<__half2*>(&u.w));
    a[0] += f0.x; a[1] += f0.y; a[2] += f1.x; a[3] += f1.y;
    a[4] += f2.x; a[5] += f2.y; a[6] += f3.x; a[7] += f3.y;
}

// ── 1. fused: degree histogram (edges) + h16 = x @ W1 (nodes, unscaled) ──
__global__ void __launch_bounds__(256) k_hist_xw1(const int* __restrict__ dst,
                                                  const float* __restrict__ x,
                                                  const float* __restrict__ W1) {
    __shared__ float W1s[5 * HID];
    int tid = threadIdx.x;
    for (int i = tid; i < 5 * HID; i += blockDim.x) W1s[i] = W1[i];
    __syncthreads();

    int t = blockIdx.x * blockDim.x + tid;
    if (t < NE) atomicAdd(&d_cnt_in[dst[t]], 1);

    int n = t >> 4, c = t & 15;
    if (n >= NN) return;
    float xv[5];
#pragma unroll
    for (int k = 0; k < 5; k++) xv[k] = x[n * 5 + k];
    float o[4];
#pragma unroll
    for (int j = 0; j < 4; j++) {
        float s = 0.f;
#pragma unroll
        for (int k = 0; k < 5; k++) s += xv[k] * W1s[k * HID + c * 4 + j];
        o[j] = s;
    }
    *reinterpret_cast<uint2*>(&d_h16[(size_t)n * HID + c * 4]) =
        pack_h4(o[0], o[1], o[2], o[3]);
}

// ── 2. single-pass scan + dinv ──
__global__ void __launch_bounds__(SCAN_T) k_scan() {
    __shared__ int sh[SCAN_T];
    int b = blockIdx.x, tid = threadIdx.x;
    int base = b * SCAN_NPB + tid * SCAN_C;
    int cnt[SCAN_C];
    int s = 0;
#pragma unroll
    for (int i = 0; i < SCAN_C; i++) {
        int idx = base + i;
        int cv = (idx < NN) ? d_cnt_in[idx] : 0;
        cnt[i] = cv;
        s += cv;
        if (idx < NN) d_dinv[idx] = rsqrtf((float)(cv + 1));  // +1 self-loop
    }
    sh[tid] = s;
    __syncthreads();
    for (int off = 1; off < SCAN_T; off <<= 1) {
        int t = (tid >= off) ? sh[tid - off] : 0;
        __syncthreads();
        sh[tid] += t;
        __syncthreads();
    }
    int toff = sh[tid] - s;
    int btotal = sh[SCAN_T - 1];
    __syncthreads();

    if (tid == 0) {
        d_agg[b] = btotal;
        __threadfence();
        atomicAdd(&d_ready, 1);
    }
    if (tid == 0) {
        while (*(volatile int*)&d_ready < SCAN_B) { }
    }
    __syncthreads();

    int v = (tid < SCAN_B) ? d_agg[tid] : 0;
    sh[tid] = v;
    __syncthreads();
    for (int off = 1; off < SCAN_T; off <<= 1) {
        int t = (tid >= off) ? sh[tid - off] : 0;
        __syncthreads();
        sh[tid] += t;
        __syncthreads();
    }
    int boff = (b > 0) ? sh[b - 1] : 0;

    int run = boff + toff;
#pragma unroll
    for (int i = 0; i < SCAN_C; i++) {
        int idx = base + i;
        if (idx < NN) { d_row[idx] = run; run += cnt[i]; }
    }
}

// ── 3. fused: CSR build (store BYTE offset) + h16 *= dinv sweep ──
__global__ void __launch_bounds__(256) k_build_scale(const int* __restrict__ src,
                                                     const int* __restrict__ dst) {
    int t = blockIdx.x * blockDim.x + threadIdx.x;
    if (t < NE) {
        int s = src[t], d = dst[t];
        int slot = d_row[d] + atomicAdd(&d_fill[d], 1);
        d_csrc[slot] = s << 7;   // s * HID * sizeof(half) = s * 128
    }
    int n = t >> 4, c = t & 15;
    if (n < NN) {
        float di = d_dinv[n];
        size_t off = (size_t)n * HID + c * 4;
        uint2 u = *reinterpret_cast<uint2*>(&d_h16[off]);
        float p0, p1, p2, p3;
        unpack_h4(u, p0, p1, p2, p3);
        *reinterpret_cast<uint2*>(&d_h16[off]) =
            pack_h4(p0 * di, p1 * di, p2 * di, p3 * di);
    }
}

// CSR gather, 8 lanes/node: lane c8 covers channels c8*8..c8*8+7 via uint4 loads.
// csrc holds byte offsets; 2-way unroll for MLP.
__device__ __forceinline__ void gather_sum8(const __half* __restrict__ feat,
                                            int start, int deg, int c8, float* a) {
    const char* fb = reinterpret_cast<const char*>(feat) + c8 * 16;
    int j = 0;
    for (; j + 2 <= deg; j += 2) {
        int o0 = __ldg(&d_csrc[start + j + 0]);
        int o1 = __ldg(&d_csrc[start + j + 1]);
        uint4 u0 = *reinterpret_cast<const uint4*>(fb + o0);
        uint4 u1 = *reinterpret_cast<const uint4*>(fb + o1);
        acc_h8(u0, a);
        acc_h8(u1, a);
    }
    if (j < deg) {
        int o = __ldg(&d_csrc[start + j]);
        uint4 u = *reinterpret_cast<const uint4*>(fb + o);
        acc_h8(u, a);
    }
}

// ── 4a. layer-1 gather (8 lanes/node): t16 = relu(dinv·(Σ hs + hs[n]) + b1) ──
__global__ void __launch_bounds__(256) k_gather1(const float* __restrict__ b1) {
    int t = blockIdx.x * blockDim.x + threadIdx.x;
    int n = t >> 3, c8 = t & 7;
    if (n >= NN) return;
    int start = d_row[n], deg = d_cnt_in[n];
    float a[8] = {};
    gather_sum8(d_h16, start, deg, c8, a);
    uint4 u = *reinterpret_cast<const uint4*>(
        reinterpret_cast<const char*>(d_h16) + ((size_t)n << 7) + c8 * 16);
    float sv[8] = {};
    acc_h8(u, sv);
    float di = d_dinv[n];
    float o[8];
#pragma unroll
    for (int k = 0; k < 8; k++)
        o[k] = fmaxf((a[k] + sv[k]) * di + __ldg(&b1[c8 * 8 + k]), 0.f);
    uint4 w;
    *reinterpret_cast<uint2*>(&w.x) = pack_h4(o[0], o[1], o[2], o[3]);
    *reinterpret_cast<uint2*>(&w.z) = pack_h4(o[4], o[5], o[6], o[7]);
    *reinterpret_cast<uint4*>(
        reinterpret_cast<char*>(d_t16) + ((size_t)n << 7) + c8 * 16) = w;
}

// ── 4b. layer-1 GEMM (register-blocked, 64 nodes/block): g16 = (t16 @ W2)·dinv ──
__global__ void __launch_bounds__(256) k_gemm(const float* __restrict__ W2) {
    __shared__ float W2s[HID * HID];
    __shared__ float h1s[64 * H1S_STRIDE];
    __shared__ float dis[64];
    int tid = threadIdx.x;
    int base = blockIdx.x * 64;
    for (int i = tid; i < HID * HID; i += 256) W2s[i] = W2[i];
    for (int i = tid; i < 64 * 16; i += 256) {
        int ln = i >> 4, c = i & 15;
        int node = base + ln;
        float p0 = 0.f, p1 = 0.f, p2 = 0.f, p3 = 0.f;
        if (node < NN) {
            uint2 u = *reinterpret_cast<const uint2*>(&d_t16[(size_t)node * HID + c * 4]);
            unpack_h4(u, p0, p1, p2, p3);
        }
        h1s[ln * H1S_STRIDE + c * 4 + 0] = p0;
        h1s[ln * H1S_STRIDE + c * 4 + 1] = p1;
        h1s[ln * H1S_STRIDE + c * 4 + 2] = p2;
        h1s[ln * H1S_STRIDE + c * 4 + 3] = p3;
    }
    if (tid < 64) dis[tid] = (base + tid < NN) ? d_dinv[base + tid] : 0.f;
    __syncthreads();

    int g = tid >> 4, c = tid & 15;
    float acc[4][4] = {};
#pragma unroll 16
    for (int k = 0; k < HID; k++) {
        float4 w = *reinterpret_cast<const float4*>(&W2s[k * HID + c * 4]);
#pragma unroll
        for (int i = 0; i < 4; i++) {
            float hv = h1s[(g * 4 + i) * H1S_STRIDE + k];
            acc[i][0] += hv * w.x;
            acc[i][1] += hv * w.y;
            acc[i][2] += hv * w.z;
            acc[i][3] += hv * w.w;
        }
    }
#pragma unroll
    for (int i = 0; i < 4; i++) {
        int node = base + g * 4 + i;
        if (node < NN) {
            float di = dis[g * 4 + i];
            *reinterpret_cast<uint2*>(&d_g16[(size_t)node * HID + c * 4]) =
                pack_h4(acc[i][0] * di, acc[i][1] * di, acc[i][2] * di, acc[i][3] * di);
        }
    }
}

// ── 5. layer 2 (8 lanes/node): h2 = relu(dinv·(Σ gs + gs[n]) + b2); pool += h2 ──
__global__ void __launch_bounds__(256) k_layer2(const float* __restrict__ b2,
                                                const int* __restrict__ batch) {
    int t = blockIdx.x * blockDim.x + threadIdx.x;
    int n = t >> 3, c8 = t & 7;
    if (n >= NN) return;
    int start = d_row[n], deg = d_cnt_in[n];
    float a[8] = {};
    gather_sum8(d_g16, start, deg, c8, a);
    uint4 u = *reinterpret_cast<const uint4*>(
        reinterpret_cast<const char*>(d_g16) + ((size_t)n << 7) + c8 * 16);
    float sv[8] = {};
    acc_h8(u, sv);
    float di = d_dinv[n];
    float o[8];
#pragma unroll
    for (int k = 0; k < 8; k++)
        o[k] = fmaxf((a[k] + sv[k]) * di + __ldg(&b2[c8 * 8 + k]), 0.f);
    int g = batch[n];
    float* pp = &d_pool[g * HID + c8 * 8];
    red_v4(pp + 0, o[0], o[1], o[2], o[3]);
    red_v4(pp + 4, o[4], o[5], o[6], o[7]);
    if (c8 == 0) atomicAdd(&d_cnt[g], 1.0f);
}

// ── 6. head + tail-restore (pool/cnt/cnt_in/fill/ready) ──
__global__ void __launch_bounds__(128) k_head(const float* __restrict__ W3,
                                              const float* __restrict__ b3,
                                              const float* __restrict__ W4,
                                              const float* __restrict__ b4,
                                              float* __restrict__ out) {
    __shared__ float p[HID];
    __shared__ float z[HID];
    int g = blockIdx.x, tid = threadIdx.x;
    if (tid < HID) {
        float cnt = fmaxf(d_cnt[g], 1.0f);
        p[tid] = d_pool[g * HID + tid] / cnt;
    }
    __syncthreads();
    if (tid < HID) d_pool[g * HID + tid] = 0.f;
    if (tid == 0)  d_cnt[g] = 0.f;
    if (g == 0 && tid == 0) d_ready = 0;
    {
        int i = g * 128 + tid;           // 262144 threads cover NN=100000
        if (i < NN) { d_cnt_in[i] = 0; d_fill[i] = 0; }
    }
    if (tid < HID) {
        float s = b3[tid];
#pragma unroll
        for (int k = 0; k < HID; k++) s += p[k] * W3[k * HID + tid];
        z[tid] = fmaxf(s, 0.f);
    }
    __syncthreads();
    float s = b4[tid];
#pragma unroll
    for (int k = 0; k < HID; k++) s += z[k] * W4[k * ODIM + tid];
    out[g * ODIM + tid] = s;
}

extern "C" void kernel_launch(void* const* d_in, const int* in_sizes, int n_in,
                              void* d_out, int out_size) {
    const float* x     = (const float*)d_in[0];
    const int*   ei    = (const int*)d_in[1];
    const int*   batch = (const int*)d_in[2];
    const float* W1 = (const float*)d_in[3];
    const float* b1 = (const float*)d_in[4];
    const float* W2 = (const float*)d_in[5];
    const float* b2 = (const float*)d_in[6];
    const float* W3 = (const float*)d_in[7];
    const float* b3 = (const float*)d_in[8];
    const float* W4 = (const float*)d_in[9];
    const float* b4 = (const float*)d_in[10];
    float* out = (float*)d_out;

    const int* src = ei;
    const int* dst = ei + NE;

    k_hist_xw1<<<(NN * 16 + 255) / 256, 256>>>(dst, x, W1);      // 0
    k_scan<<<SCAN_B, SCAN_T>>>();                                // 1
    k_build_scale<<<(NN * 16 + 255) / 256, 256>>>(src, dst);     // 2
    k_gather1<<<(NN * 8 + 255) / 256, 256>>>(b1);                // 3 ← profiled slot
    k_gemm<<<(NN + 63) / 64, 256>>>(W2);                         // 4
    k_layer2<<<(NN * 8 + 255) / 256, 256>>>(b2, batch);          // 5
    k_head<<<NG, 128>>>(W3, b3, W4, b4, out);                    // 6
}